// round 2
// baseline (speedup 1.0000x reference)
#include <cuda_runtime.h>
#include <math.h>
#include <stdint.h>

#define BB 16
#define DD 2048
#define NH 32
#define NKV 8
#define HDIM 64
#define GRP 4
#define TSEQ 4096
#define HIDDEN 5632
#define KVD 512   // NKV*HDIM

// ---------------- scratch (device globals; no allocation allowed) ----------------
__device__ float g_xn[BB * DD];
__device__ float g_q[BB * DD];
__device__ float g_k[BB * KVD];
__device__ float g_v[BB * KVD];
__device__ float g_attn[BB * DD];
__device__ float g_h[BB * DD];
__device__ float g_hn[BB * DD];
__device__ float g_ff1[BB * HIDDEN];
__device__ float g_scores[BB * NKV * GRP * TSEQ];   // 8 MB

// ---------------- helpers ----------------
__device__ __forceinline__ float warp_sum(float v) {
    v += __shfl_down_sync(0xffffffffu, v, 16);
    v += __shfl_down_sync(0xffffffffu, v, 8);
    v += __shfl_down_sync(0xffffffffu, v, 4);
    v += __shfl_down_sync(0xffffffffu, v, 2);
    v += __shfl_down_sync(0xffffffffu, v, 1);
    return v;
}

// Accumulate acc[b][j] += dot(A[b,:], W[o0+j,:]) over K, warp-cooperative.
__device__ __forceinline__ void gemv_core(const float* __restrict__ A,
                                          const float* __restrict__ W,
                                          int o0, int K, int lane,
                                          float acc[16][4]) {
    const float4* w0 = (const float4*)(W + (size_t)(o0 + 0) * K);
    const float4* w1 = (const float4*)(W + (size_t)(o0 + 1) * K);
    const float4* w2 = (const float4*)(W + (size_t)(o0 + 2) * K);
    const float4* w3 = (const float4*)(W + (size_t)(o0 + 3) * K);
    int K4 = K >> 2;
    for (int c = lane; c < K4; c += 32) {
        float4 a0 = w0[c], a1 = w1[c], a2 = w2[c], a3 = w3[c];
#pragma unroll
        for (int b = 0; b < 16; b++) {
            float4 xv = ((const float4*)(A + (size_t)b * K))[c];
            acc[b][0] += a0.x * xv.x + a0.y * xv.y + a0.z * xv.z + a0.w * xv.w;
            acc[b][1] += a1.x * xv.x + a1.y * xv.y + a1.z * xv.z + a1.w * xv.w;
            acc[b][2] += a2.x * xv.x + a2.y * xv.y + a2.z * xv.z + a2.w * xv.w;
            acc[b][3] += a3.x * xv.x + a3.y * xv.y + a3.z * xv.z + a3.w * xv.w;
        }
    }
}

// ---------------- kernels ----------------
// rmsnorm variant 1: input from harness pointer x -> g_xn  (device globals
// referenced ONLY inside device code; passing __device__ symbols as host-side
// kernel args silently writes to the host shadow on GB300/ATS).
__global__ void rmsnorm_x_kernel(const float* __restrict__ x,
                                 const float* __restrict__ w) {
    int b = blockIdx.x;
    const float* xr = x + (size_t)b * DD;
    float s = 0.f;
    for (int i = threadIdx.x; i < DD; i += 256) { float v = xr[i]; s += v * v; }
    for (int off = 16; off; off >>= 1) s += __shfl_xor_sync(0xffffffffu, s, off);
    __shared__ float red[8];
    int lane = threadIdx.x & 31, wid = threadIdx.x >> 5;
    if (lane == 0) red[wid] = s;
    __syncthreads();
    if (threadIdx.x == 0) {
        float t = 0.f;
#pragma unroll
        for (int i = 0; i < 8; i++) t += red[i];
        red[0] = rsqrtf(t * (1.0f / DD) + 1e-6f);
    }
    __syncthreads();
    float inv = red[0];
    float* orow = g_xn + (size_t)b * DD;
    for (int i = threadIdx.x; i < DD; i += 256) orow[i] = xr[i] * inv * w[i];
}

// rmsnorm variant 2: g_h -> g_hn
__global__ void rmsnorm_h_kernel(const float* __restrict__ w) {
    int b = blockIdx.x;
    const float* xr = g_h + (size_t)b * DD;
    float s = 0.f;
    for (int i = threadIdx.x; i < DD; i += 256) { float v = xr[i]; s += v * v; }
    for (int off = 16; off; off >>= 1) s += __shfl_xor_sync(0xffffffffu, s, off);
    __shared__ float red[8];
    int lane = threadIdx.x & 31, wid = threadIdx.x >> 5;
    if (lane == 0) red[wid] = s;
    __syncthreads();
    if (threadIdx.x == 0) {
        float t = 0.f;
#pragma unroll
        for (int i = 0; i < 8; i++) t += red[i];
        red[0] = rsqrtf(t * (1.0f / DD) + 1e-6f);
    }
    __syncthreads();
    float inv = red[0];
    float* orow = g_hn + (size_t)b * DD;
    for (int i = threadIdx.x; i < DD; i += 256) orow[i] = xr[i] * inv * w[i];
}

__global__ __launch_bounds__(128, 4) void gemv_qkv_kernel(
    const float* __restrict__ wq, const float* __restrict__ wk,
    const float* __restrict__ wv) {
    int lane = threadIdx.x & 31, w = threadIdx.x >> 5;
    int o = blockIdx.x * 16 + w * 4;
    const float* W; float* C; int oo, cst;
    if (o < 2048)      { W = wq; C = g_q; oo = o;        cst = DD;  }
    else if (o < 2560) { W = wk; C = g_k; oo = o - 2048; cst = KVD; }
    else               { W = wv; C = g_v; oo = o - 2560; cst = KVD; }
    float acc[16][4];
#pragma unroll
    for (int b = 0; b < 16; b++) { acc[b][0]=0;acc[b][1]=0;acc[b][2]=0;acc[b][3]=0; }
    gemv_core(g_xn, W, oo, DD, lane, acc);
#pragma unroll
    for (int b = 0; b < 16; b++)
#pragma unroll
        for (int j = 0; j < 4; j++) {
            float v = warp_sum(acc[b][j]);
            if (lane == 0) C[(size_t)b * cst + oo + j] = v;
        }
}

__global__ void rope_kernel(const float* __restrict__ cosv,
                            const float* __restrict__ sinv) {
    int idx = blockIdx.x * 256 + threadIdx.x;
    if (idx >= BB * 48 * 32) return;
    int b = idx / (48 * 32);
    int r = idx % (48 * 32);
    int head = r >> 5;
    int i = r & 31;
    float c = cosv[i], s = sinv[i];
    float* ptr;
    if (head < 32)      ptr = g_q + (size_t)b * DD  + head * 64;
    else if (head < 40) ptr = g_k + (size_t)b * KVD + (head - 32) * 64;
    else                ptr = g_v + (size_t)b * KVD + (head - 40) * 64;
    float x0 = ptr[2 * i], x1 = ptr[2 * i + 1];
    ptr[2 * i]     = x0 * c - x1 * s;
    ptr[2 * i + 1] = x0 * s + x1 * c;
}

__global__ __launch_bounds__(256) void attn_kernel(
    const float* __restrict__ cache_k, const float* __restrict__ cache_v) {
    int pair = blockIdx.x;             // b*8 + kv
    int b = pair >> 3, kv = pair & 7;
    int tid = threadIdx.x, lane = tid & 31, wid = tid >> 5;

    __shared__ float q_s[4][64];
    __shared__ float red[4][8];
    __shared__ float m_s[4], inv_s[4];

    { // load + scale q
        int g = tid >> 6, d = tid & 63;
        q_s[g][d] = g_q[(size_t)b * DD + (kv * 4 + g) * 64 + d] * 0.125f;
    }
    __syncthreads();

    int c = lane & 3, p = lane >> 2;
    float qr[4][16];
#pragma unroll
    for (int g = 0; g < 4; g++)
#pragma unroll
        for (int j = 0; j < 16; j++) qr[g][j] = q_s[g][c * 16 + j];

    float* sc = g_scores + (size_t)pair * 4 * TSEQ;
    const float* kbase = cache_k + ((size_t)b * TSEQ * NKV + kv) * HDIM;
    const float* knew  = g_k + (size_t)(b * NKV + kv) * HDIM;

    // phase 1: scores[g][t]
    for (int t0 = wid * 8; t0 < TSEQ; t0 += 64) {
        int t = t0 + p;
        const float* krow = (t < TSEQ - 1) ? (kbase + (size_t)t * KVD) : knew;
        const float4* k4 = (const float4*)(krow + c * 16);
        float4 k0 = k4[0], k1 = k4[1], k2 = k4[2], k3 = k4[3];
        float kv16[16] = {k0.x,k0.y,k0.z,k0.w, k1.x,k1.y,k1.z,k1.w,
                          k2.x,k2.y,k2.z,k2.w, k3.x,k3.y,k3.z,k3.w};
        float s[4];
#pragma unroll
        for (int g = 0; g < 4; g++) {
            float acc = 0.f;
#pragma unroll
            for (int j = 0; j < 16; j++) acc += qr[g][j] * kv16[j];
            s[g] = acc;
        }
#pragma unroll
        for (int g = 0; g < 4; g++) {
            s[g] += __shfl_xor_sync(0xffffffffu, s[g], 1);
            s[g] += __shfl_xor_sync(0xffffffffu, s[g], 2);
        }
        if (c == 0) {
#pragma unroll
            for (int g = 0; g < 4; g++) sc[g * TSEQ + t] = s[g];
        }
    }
    __syncthreads();

    // phase 2: softmax (max, exp, sum)
    float lm[4] = {-1e30f, -1e30f, -1e30f, -1e30f};
    for (int i = tid; i < TSEQ; i += 256) {
#pragma unroll
        for (int g = 0; g < 4; g++) lm[g] = fmaxf(lm[g], sc[g * TSEQ + i]);
    }
#pragma unroll
    for (int g = 0; g < 4; g++) {
        for (int off = 16; off; off >>= 1)
            lm[g] = fmaxf(lm[g], __shfl_xor_sync(0xffffffffu, lm[g], off));
        if (lane == 0) red[g][wid] = lm[g];
    }
    __syncthreads();
    if (tid < 4) {
        float m = -1e30f;
#pragma unroll
        for (int w = 0; w < 8; w++) m = fmaxf(m, red[tid][w]);
        m_s[tid] = m;
    }
    __syncthreads();
    float ls[4] = {0.f, 0.f, 0.f, 0.f};
    for (int i = tid; i < TSEQ; i += 256) {
#pragma unroll
        for (int g = 0; g < 4; g++) {
            float e = __expf(sc[g * TSEQ + i] - m_s[g]);
            sc[g * TSEQ + i] = e;
            ls[g] += e;
        }
    }
#pragma unroll
    for (int g = 0; g < 4; g++) {
        ls[g] = warp_sum(ls[g]);
        if (lane == 0) red[g][wid] = ls[g];
    }
    __syncthreads();
    if (tid < 4) {
        float s = 0.f;
#pragma unroll
        for (int w = 0; w < 8; w++) s += red[tid][w];
        inv_s[tid] = 1.0f / s;
    }
    __syncthreads();

    // phase 3: PV
    int g = tid >> 6, d = tid & 63;
    const float* vbase = cache_v + ((size_t)b * TSEQ * NKV + kv) * HDIM + d;
    const float* pg = sc + (size_t)g * TSEQ;
    float a0 = 0.f, a1 = 0.f, a2 = 0.f, a3 = 0.f;
    for (int t = 0; t < TSEQ - 4; t += 4) {
        float4 pv = *(const float4*)(pg + t);
        a0 += pv.x * vbase[(size_t)(t + 0) * KVD];
        a1 += pv.y * vbase[(size_t)(t + 1) * KVD];
        a2 += pv.z * vbase[(size_t)(t + 2) * KVD];
        a3 += pv.w * vbase[(size_t)(t + 3) * KVD];
    }
    {
        int t = TSEQ - 4;
        float4 pv = *(const float4*)(pg + t);
        a0 += pv.x * vbase[(size_t)(t + 0) * KVD];
        a1 += pv.y * vbase[(size_t)(t + 1) * KVD];
        a2 += pv.z * vbase[(size_t)(t + 2) * KVD];
        a3 += pv.w * g_v[(size_t)(b * NKV + kv) * HDIM + d];   // new token V
    }
    float r = (a0 + a1 + a2 + a3) * inv_s[g];
    g_attn[(size_t)b * DD + (kv * 4 + g) * 64 + d] = r;
}

__global__ __launch_bounds__(128, 4) void gemv_wo_kernel(
    const float* __restrict__ wo, const float* __restrict__ x) {
    int lane = threadIdx.x & 31, w = threadIdx.x >> 5;
    int o = blockIdx.x * 16 + w * 4;
    float acc[16][4];
#pragma unroll
    for (int b = 0; b < 16; b++) { acc[b][0]=0;acc[b][1]=0;acc[b][2]=0;acc[b][3]=0; }
    gemv_core(g_attn, wo, o, DD, lane, acc);
#pragma unroll
    for (int b = 0; b < 16; b++)
#pragma unroll
        for (int j = 0; j < 4; j++) {
            float v = warp_sum(acc[b][j]);
            if (lane == 0) g_h[(size_t)b * DD + o + j] = v + x[(size_t)b * DD + o + j];
        }
}

__global__ __launch_bounds__(128, 4) void gemv_w1_kernel(const float* __restrict__ w1) {
    int lane = threadIdx.x & 31, w = threadIdx.x >> 5;
    int o = blockIdx.x * 16 + w * 4;
    float acc[16][4];
#pragma unroll
    for (int b = 0; b < 16; b++) { acc[b][0]=0;acc[b][1]=0;acc[b][2]=0;acc[b][3]=0; }
    gemv_core(g_hn, w1, o, DD, lane, acc);
#pragma unroll
    for (int b = 0; b < 16; b++)
#pragma unroll
        for (int j = 0; j < 4; j++) {
            float v = warp_sum(acc[b][j]);
            if (lane == 0) g_ff1[(size_t)b * HIDDEN + o + j] = v / (1.0f + __expf(-v));
        }
}

__global__ __launch_bounds__(128, 4) void gemv_out_kernel(
    const float* __restrict__ w2, const float* __restrict__ w3,
    float* __restrict__ out) {
    int lane = threadIdx.x & 31, w = threadIdx.x >> 5;
    int o = blockIdx.x * 16 + w * 4;
    float acc[16][4];
#pragma unroll
    for (int b = 0; b < 16; b++) { acc[b][0]=0;acc[b][1]=0;acc[b][2]=0;acc[b][3]=0; }
    gemv_core(g_ff1, w2, o, HIDDEN, lane, acc);
    gemv_core(g_hn,  w3, o, DD,     lane, acc);
#pragma unroll
    for (int b = 0; b < 16; b++)
#pragma unroll
        for (int j = 0; j < 4; j++) {
            float v = warp_sum(acc[b][j]);
            if (lane == 0) out[(size_t)b * DD + o + j] = g_h[(size_t)b * DD + o + j] + v;
        }
}

// ---------------- launch ----------------
extern "C" void kernel_launch(void* const* d_in, const int* in_sizes, int n_in,
                              void* d_out, int out_size) {
    const float* x         = (const float*)d_in[0];
    const float* freqs_cos = (const float*)d_in[1];
    const float* freqs_sin = (const float*)d_in[2];
    const float* cache_k   = (const float*)d_in[3];
    const float* cache_v   = (const float*)d_in[4];
    const float* wq_w      = (const float*)d_in[5];
    const float* wk_w      = (const float*)d_in[6];
    const float* wv_w      = (const float*)d_in[7];
    const float* wo_w      = (const float*)d_in[8];
    const float* w1_w      = (const float*)d_in[9];
    const float* w2_w      = (const float*)d_in[10];
    const float* w3_w      = (const float*)d_in[11];
    const float* attn_nw   = (const float*)d_in[12];
    const float* ffn_nw    = (const float*)d_in[13];
    float* out = (float*)d_out;

    // 1. xn = rmsnorm(x)
    rmsnorm_x_kernel<<<BB, 256>>>(x, attn_nw);
    // 2. q/k/v = xn @ {wq,wk,wv}.T
    gemv_qkv_kernel<<<192, 128>>>(wq_w, wk_w, wv_w);
    // 3. RoPE on q, k, v
    rope_kernel<<<(BB * 48 * 32 + 255) / 256, 256>>>(freqs_cos, freqs_sin);
    // 4. attention (T=4096; last position from g_k/g_v)
    attn_kernel<<<BB * NKV, 256>>>(cache_k, cache_v);
    // 5. h = x + attn @ wo.T
    gemv_wo_kernel<<<128, 128>>>(wo_w, x);
    // 6. hn = rmsnorm(h)
    rmsnorm_h_kernel<<<BB, 256>>>(ffn_nw);
    // 7. ff1 = silu(hn @ w1.T)
    gemv_w1_kernel<<<HIDDEN / 16, 128>>>(w1_w);
    // 8. out = h + ff1 @ w2.T + hn @ w3.T
    gemv_out_kernel<<<128, 128>>>(w2_w, w3_w, out);
}

// round 3
// speedup vs baseline: 1.0070x; 1.0070x over previous
#include <cuda_runtime.h>
#include <math.h>
#include <stdint.h>

#define BB 16
#define DD 2048
#define NH 32
#define NKV 8
#define HDIM 64
#define GRP 4
#define TSEQ 4096
#define HIDDEN 5632
#define KVD 512   // NKV*HDIM

// ---------------- scratch (device globals; no allocation allowed) ----------------
__device__ float g_xn[BB * DD];
__device__ float g_q[BB * DD];
__device__ float g_k[BB * KVD];
__device__ float g_v[BB * KVD];
__device__ float g_attn[BB * DD];
__device__ float g_h[BB * DD];
__device__ float g_hn[BB * DD];
__device__ float g_ff1[BB * HIDDEN];
__device__ float g_scores[BB * NKV * GRP * TSEQ];   // 8 MB

// ---------------- helpers ----------------
__device__ __forceinline__ float warp_sum(float v) {
    v += __shfl_down_sync(0xffffffffu, v, 16);
    v += __shfl_down_sync(0xffffffffu, v, 8);
    v += __shfl_down_sync(0xffffffffu, v, 4);
    v += __shfl_down_sync(0xffffffffu, v, 2);
    v += __shfl_down_sync(0xffffffffu, v, 1);
    return v;
}

// Accumulate acc[b][j] += dot(A[b,:], W[o0+j,:]) over K, warp-cooperative.
__device__ __forceinline__ void gemv_core(const float* __restrict__ A,
                                          const float* __restrict__ W,
                                          int o0, int K, int lane,
                                          float acc[16][4]) {
    const float4* w0 = (const float4*)(W + (size_t)(o0 + 0) * K);
    const float4* w1 = (const float4*)(W + (size_t)(o0 + 1) * K);
    const float4* w2 = (const float4*)(W + (size_t)(o0 + 2) * K);
    const float4* w3 = (const float4*)(W + (size_t)(o0 + 3) * K);
    int K4 = K >> 2;
    for (int c = lane; c < K4; c += 32) {
        float4 a0 = w0[c], a1 = w1[c], a2 = w2[c], a3 = w3[c];
#pragma unroll
        for (int b = 0; b < 16; b++) {
            float4 xv = ((const float4*)(A + (size_t)b * K))[c];
            acc[b][0] += a0.x * xv.x + a0.y * xv.y + a0.z * xv.z + a0.w * xv.w;
            acc[b][1] += a1.x * xv.x + a1.y * xv.y + a1.z * xv.z + a1.w * xv.w;
            acc[b][2] += a2.x * xv.x + a2.y * xv.y + a2.z * xv.z + a2.w * xv.w;
            acc[b][3] += a3.x * xv.x + a3.y * xv.y + a3.z * xv.z + a3.w * xv.w;
        }
    }
}

// ---------------- kernels ----------------
// rmsnorm variant 1: input from harness pointer x -> g_xn  (device globals
// referenced ONLY inside device code; passing __device__ symbols as host-side
// kernel args silently writes to the host shadow on GB300/ATS).
__global__ void rmsnorm_x_kernel(const float* __restrict__ x,
                                 const float* __restrict__ w) {
    int b = blockIdx.x;
    const float* xr = x + (size_t)b * DD;
    float s = 0.f;
    for (int i = threadIdx.x; i < DD; i += 256) { float v = xr[i]; s += v * v; }
    for (int off = 16; off; off >>= 1) s += __shfl_xor_sync(0xffffffffu, s, off);
    __shared__ float red[8];
    int lane = threadIdx.x & 31, wid = threadIdx.x >> 5;
    if (lane == 0) red[wid] = s;
    __syncthreads();
    if (threadIdx.x == 0) {
        float t = 0.f;
#pragma unroll
        for (int i = 0; i < 8; i++) t += red[i];
        red[0] = rsqrtf(t * (1.0f / DD) + 1e-6f);
    }
    __syncthreads();
    float inv = red[0];
    float* orow = g_xn + (size_t)b * DD;
    for (int i = threadIdx.x; i < DD; i += 256) orow[i] = xr[i] * inv * w[i];
}

// rmsnorm variant 2: g_h -> g_hn
__global__ void rmsnorm_h_kernel(const float* __restrict__ w) {
    int b = blockIdx.x;
    const float* xr = g_h + (size_t)b * DD;
    float s = 0.f;
    for (int i = threadIdx.x; i < DD; i += 256) { float v = xr[i]; s += v * v; }
    for (int off = 16; off; off >>= 1) s += __shfl_xor_sync(0xffffffffu, s, off);
    __shared__ float red[8];
    int lane = threadIdx.x & 31, wid = threadIdx.x >> 5;
    if (lane == 0) red[wid] = s;
    __syncthreads();
    if (threadIdx.x == 0) {
        float t = 0.f;
#pragma unroll
        for (int i = 0; i < 8; i++) t += red[i];
        red[0] = rsqrtf(t * (1.0f / DD) + 1e-6f);
    }
    __syncthreads();
    float inv = red[0];
    float* orow = g_hn + (size_t)b * DD;
    for (int i = threadIdx.x; i < DD; i += 256) orow[i] = xr[i] * inv * w[i];
}

__global__ __launch_bounds__(128, 4) void gemv_qkv_kernel(
    const float* __restrict__ wq, const float* __restrict__ wk,
    const float* __restrict__ wv) {
    int lane = threadIdx.x & 31, w = threadIdx.x >> 5;
    int o = blockIdx.x * 16 + w * 4;
    const float* W; float* C; int oo, cst;
    if (o < 2048)      { W = wq; C = g_q; oo = o;        cst = DD;  }
    else if (o < 2560) { W = wk; C = g_k; oo = o - 2048; cst = KVD; }
    else               { W = wv; C = g_v; oo = o - 2560; cst = KVD; }
    float acc[16][4];
#pragma unroll
    for (int b = 0; b < 16; b++) { acc[b][0]=0;acc[b][1]=0;acc[b][2]=0;acc[b][3]=0; }
    gemv_core(g_xn, W, oo, DD, lane, acc);
#pragma unroll
    for (int b = 0; b < 16; b++)
#pragma unroll
        for (int j = 0; j < 4; j++) {
            float v = warp_sum(acc[b][j]);
            if (lane == 0) C[(size_t)b * cst + oo + j] = v;
        }
}

__global__ void rope_kernel(const float* __restrict__ cosv,
                            const float* __restrict__ sinv) {
    int idx = blockIdx.x * 256 + threadIdx.x;
    if (idx >= BB * 48 * 32) return;
    int b = idx / (48 * 32);
    int r = idx % (48 * 32);
    int head = r >> 5;
    int i = r & 31;
    float c = cosv[i], s = sinv[i];
    float* ptr;
    if (head < 32)      ptr = g_q + (size_t)b * DD  + head * 64;
    else if (head < 40) ptr = g_k + (size_t)b * KVD + (head - 32) * 64;
    else                ptr = g_v + (size_t)b * KVD + (head - 40) * 64;
    float x0 = ptr[2 * i], x1 = ptr[2 * i + 1];
    ptr[2 * i]     = x0 * c - x1 * s;
    ptr[2 * i + 1] = x0 * s + x1 * c;
}

__global__ __launch_bounds__(256) void attn_kernel(
    const float* __restrict__ cache_k, const float* __restrict__ cache_v) {
    int pair = blockIdx.x;             // b*8 + kv
    int b = pair >> 3, kv = pair & 7;
    int tid = threadIdx.x, lane = tid & 31, wid = tid >> 5;

    __shared__ float q_s[4][64];
    __shared__ float red[4][8];
    __shared__ float m_s[4], inv_s[4];

    { // load + scale q
        int g = tid >> 6, d = tid & 63;
        q_s[g][d] = g_q[(size_t)b * DD + (kv * 4 + g) * 64 + d] * 0.125f;
    }
    __syncthreads();

    int c = lane & 3, p = lane >> 2;
    float qr[4][16];
#pragma unroll
    for (int g = 0; g < 4; g++)
#pragma unroll
        for (int j = 0; j < 16; j++) qr[g][j] = q_s[g][c * 16 + j];

    float* sc = g_scores + (size_t)pair * 4 * TSEQ;
    const float* kbase = cache_k + ((size_t)b * TSEQ * NKV + kv) * HDIM;
    const float* knew  = g_k + (size_t)(b * NKV + kv) * HDIM;

    // phase 1: scores[g][t]
    for (int t0 = wid * 8; t0 < TSEQ; t0 += 64) {
        int t = t0 + p;
        const float* krow = (t < TSEQ - 1) ? (kbase + (size_t)t * KVD) : knew;
        const float4* k4 = (const float4*)(krow + c * 16);
        float4 k0 = k4[0], k1 = k4[1], k2 = k4[2], k3 = k4[3];
        float kv16[16] = {k0.x,k0.y,k0.z,k0.w, k1.x,k1.y,k1.z,k1.w,
                          k2.x,k2.y,k2.z,k2.w, k3.x,k3.y,k3.z,k3.w};
        float s[4];
#pragma unroll
        for (int g = 0; g < 4; g++) {
            float acc = 0.f;
#pragma unroll
            for (int j = 0; j < 16; j++) acc += qr[g][j] * kv16[j];
            s[g] = acc;
        }
#pragma unroll
        for (int g = 0; g < 4; g++) {
            s[g] += __shfl_xor_sync(0xffffffffu, s[g], 1);
            s[g] += __shfl_xor_sync(0xffffffffu, s[g], 2);
        }
        if (c == 0) {
#pragma unroll
            for (int g = 0; g < 4; g++) sc[g * TSEQ + t] = s[g];
        }
    }
    __syncthreads();

    // phase 2: softmax (max, exp, sum)
    float lm[4] = {-1e30f, -1e30f, -1e30f, -1e30f};
    for (int i = tid; i < TSEQ; i += 256) {
#pragma unroll
        for (int g = 0; g < 4; g++) lm[g] = fmaxf(lm[g], sc[g * TSEQ + i]);
    }
#pragma unroll
    for (int g = 0; g < 4; g++) {
        for (int off = 16; off; off >>= 1)
            lm[g] = fmaxf(lm[g], __shfl_xor_sync(0xffffffffu, lm[g], off));
        if (lane == 0) red[g][wid] = lm[g];
    }
    __syncthreads();
    if (tid < 4) {
        float m = -1e30f;
#pragma unroll
        for (int w = 0; w < 8; w++) m = fmaxf(m, red[tid][w]);
        m_s[tid] = m;
    }
    __syncthreads();
    float ls[4] = {0.f, 0.f, 0.f, 0.f};
    for (int i = tid; i < TSEQ; i += 256) {
#pragma unroll
        for (int g = 0; g < 4; g++) {
            float e = __expf(sc[g * TSEQ + i] - m_s[g]);
            sc[g * TSEQ + i] = e;
            ls[g] += e;
        }
    }
#pragma unroll
    for (int g = 0; g < 4; g++) {
        ls[g] = warp_sum(ls[g]);
        if (lane == 0) red[g][wid] = ls[g];
    }
    __syncthreads();
    if (tid < 4) {
        float s = 0.f;
#pragma unroll
        for (int w = 0; w < 8; w++) s += red[tid][w];
        inv_s[tid] = 1.0f / s;
    }
    __syncthreads();

    // phase 3: PV
    int g = tid >> 6, d = tid & 63;
    const float* vbase = cache_v + ((size_t)b * TSEQ * NKV + kv) * HDIM + d;
    const float* pg = sc + (size_t)g * TSEQ;
    float a0 = 0.f, a1 = 0.f, a2 = 0.f, a3 = 0.f;
    for (int t = 0; t < TSEQ - 4; t += 4) {
        float4 pv = *(const float4*)(pg + t);
        a0 += pv.x * vbase[(size_t)(t + 0) * KVD];
        a1 += pv.y * vbase[(size_t)(t + 1) * KVD];
        a2 += pv.z * vbase[(size_t)(t + 2) * KVD];
        a3 += pv.w * vbase[(size_t)(t + 3) * KVD];
    }
    {
        int t = TSEQ - 4;
        float4 pv = *(const float4*)(pg + t);
        a0 += pv.x * vbase[(size_t)(t + 0) * KVD];
        a1 += pv.y * vbase[(size_t)(t + 1) * KVD];
        a2 += pv.z * vbase[(size_t)(t + 2) * KVD];
        a3 += pv.w * g_v[(size_t)(b * NKV + kv) * HDIM + d];   // new token V
    }
    float r = (a0 + a1 + a2 + a3) * inv_s[g];
    g_attn[(size_t)b * DD + (kv * 4 + g) * 64 + d] = r;
}

__global__ __launch_bounds__(128, 4) void gemv_wo_kernel(
    const float* __restrict__ wo, const float* __restrict__ x) {
    int lane = threadIdx.x & 31, w = threadIdx.x >> 5;
    int o = blockIdx.x * 16 + w * 4;
    float acc[16][4];
#pragma unroll
    for (int b = 0; b < 16; b++) { acc[b][0]=0;acc[b][1]=0;acc[b][2]=0;acc[b][3]=0; }
    gemv_core(g_attn, wo, o, DD, lane, acc);
#pragma unroll
    for (int b = 0; b < 16; b++)
#pragma unroll
        for (int j = 0; j < 4; j++) {
            float v = warp_sum(acc[b][j]);
            if (lane == 0) g_h[(size_t)b * DD + o + j] = v + x[(size_t)b * DD + o + j];
        }
}

__global__ __launch_bounds__(128, 4) void gemv_w1_kernel(const float* __restrict__ w1) {
    int lane = threadIdx.x & 31, w = threadIdx.x >> 5;
    int o = blockIdx.x * 16 + w * 4;
    float acc[16][4];
#pragma unroll
    for (int b = 0; b < 16; b++) { acc[b][0]=0;acc[b][1]=0;acc[b][2]=0;acc[b][3]=0; }
    gemv_core(g_hn, w1, o, DD, lane, acc);
#pragma unroll
    for (int b = 0; b < 16; b++)
#pragma unroll
        for (int j = 0; j < 4; j++) {
            float v = warp_sum(acc[b][j]);
            if (lane == 0) g_ff1[(size_t)b * HIDDEN + o + j] = v / (1.0f + __expf(-v));
        }
}

__global__ __launch_bounds__(128, 4) void gemv_out_kernel(
    const float* __restrict__ w2, const float* __restrict__ w3,
    float* __restrict__ out) {
    int lane = threadIdx.x & 31, w = threadIdx.x >> 5;
    int o = blockIdx.x * 16 + w * 4;
    float acc[16][4];
#pragma unroll
    for (int b = 0; b < 16; b++) { acc[b][0]=0;acc[b][1]=0;acc[b][2]=0;acc[b][3]=0; }
    gemv_core(g_ff1, w2, o, HIDDEN, lane, acc);
    gemv_core(g_hn,  w3, o, DD,     lane, acc);
#pragma unroll
    for (int b = 0; b < 16; b++)
#pragma unroll
        for (int j = 0; j < 4; j++) {
            float v = warp_sum(acc[b][j]);
            if (lane == 0) out[(size_t)b * DD + o + j] = g_h[(size_t)b * DD + o + j] + v;
        }
}

// ---------------- launch ----------------
extern "C" void kernel_launch(void* const* d_in, const int* in_sizes, int n_in,
                              void* d_out, int out_size) {
    const float* x         = (const float*)d_in[0];
    const float* freqs_cos = (const float*)d_in[1];
    const float* freqs_sin = (const float*)d_in[2];
    const float* cache_k   = (const float*)d_in[3];
    const float* cache_v   = (const float*)d_in[4];
    const float* wq_w      = (const float*)d_in[5];
    const float* wk_w      = (const float*)d_in[6];
    const float* wv_w      = (const float*)d_in[7];
    const float* wo_w      = (const float*)d_in[8];
    const float* w1_w      = (const float*)d_in[9];
    const float* w2_w      = (const float*)d_in[10];
    const float* w3_w      = (const float*)d_in[11];
    const float* attn_nw   = (const float*)d_in[12];
    const float* ffn_nw    = (const float*)d_in[13];
    float* out = (float*)d_out;

    // 1. xn = rmsnorm(x)
    rmsnorm_x_kernel<<<BB, 256>>>(x, attn_nw);
    // 2. q/k/v = xn @ {wq,wk,wv}.T
    gemv_qkv_kernel<<<192, 128>>>(wq_w, wk_w, wv_w);
    // 3. RoPE on q, k, v
    rope_kernel<<<(BB * 48 * 32 + 255) / 256, 256>>>(freqs_cos, freqs_sin);
    // 4. attention (T=4096; last position from g_k/g_v)
    attn_kernel<<<BB * NKV, 256>>>(cache_k, cache_v);
    // 5. h = x + attn @ wo.T
    gemv_wo_kernel<<<128, 128>>>(wo_w, x);
    // 6. hn = rmsnorm(h)
    rmsnorm_h_kernel<<<BB, 256>>>(ffn_nw);
    // 7. ff1 = silu(hn @ w1.T)
    gemv_w1_kernel<<<HIDDEN / 16, 128>>>(w1_w);
    // 8. out = h + ff1 @ w2.T + hn @ w3.T
    gemv_out_kernel<<<128, 128>>>(w2_w, w3_w, out);
}